// round 2
// baseline (speedup 1.0000x reference)
#include <cuda_runtime.h>
#include <cuda_bf16.h>
#include <math.h>

// Problem dims
#define B_ 4
#define S_ 2048
#define T_ 8192      // B*S tokens
#define D_ 768
#define H_ 3072
#define E_ 8

#define TILE 128
#define KC 8
#define MAX_MT 72    // worst-case sum over experts of ceil(n_e/128) = 64 + 7

// ---------------- scratch (no allocations allowed) ----------------
__device__ int   g_expert_idx[T_];
__device__ int   g_counts[E_];
__device__ int   g_offs[E_ + 1];
__device__ int   g_cursor[E_];
__device__ int   g_perm[T_];
__device__ int   g_tile_expert[MAX_MT];
__device__ int   g_tile_row0[MAX_MT];
__device__ int   g_tile_rows[MAX_MT];
__device__ __align__(16) float g_h[(size_t)T_ * H_];   // ~100 MB hidden scratch

// ---------------- kernel 0: init ----------------
__global__ void init_kernel() {
    int i = threadIdx.x;
    if (i < E_) g_counts[i] = 0;
}

// ---------------- kernel 1: gating (argmax(x@Wg + bg + gumbel)) ----------------
__global__ void gate_kernel(const float* __restrict__ x,
                            const float* __restrict__ gumbel,
                            const float* __restrict__ Wg,
                            const float* __restrict__ bg) {
    int warp = (blockIdx.x * blockDim.x + threadIdx.x) >> 5;
    int lane = threadIdx.x & 31;
    if (warp >= T_) return;
    const float* xr = x + (size_t)warp * D_;
    float acc[E_];
#pragma unroll
    for (int e = 0; e < E_; e++) acc[e] = 0.f;
    for (int d = lane; d < D_; d += 32) {
        float xv = xr[d];
        float4 w0 = *(const float4*)(Wg + d * E_);
        float4 w1 = *(const float4*)(Wg + d * E_ + 4);
        acc[0] = fmaf(xv, w0.x, acc[0]);
        acc[1] = fmaf(xv, w0.y, acc[1]);
        acc[2] = fmaf(xv, w0.z, acc[2]);
        acc[3] = fmaf(xv, w0.w, acc[3]);
        acc[4] = fmaf(xv, w1.x, acc[4]);
        acc[5] = fmaf(xv, w1.y, acc[5]);
        acc[6] = fmaf(xv, w1.z, acc[6]);
        acc[7] = fmaf(xv, w1.w, acc[7]);
    }
#pragma unroll
    for (int e = 0; e < E_; e++) {
#pragma unroll
        for (int off = 16; off; off >>= 1)
            acc[e] += __shfl_xor_sync(0xFFFFFFFFu, acc[e], off);
    }
    if (lane == 0) {
        const float* g = gumbel + (size_t)warp * E_;
        int best = 0;
        float bv = acc[0] + bg[0] + g[0];
#pragma unroll
        for (int e = 1; e < E_; e++) {
            float v = acc[e] + bg[e] + g[e];
            if (v > bv) { bv = v; best = e; }  // strict > keeps first max (jnp.argmax)
        }
        g_expert_idx[warp] = best;
        atomicAdd(&g_counts[best], 1);
    }
}

// ---------------- kernel 2: scan + tile table ----------------
__global__ void scan_kernel() {
    if (threadIdx.x != 0) return;
    int off = 0, nt = 0;
    for (int e = 0; e < E_; e++) {
        g_offs[e] = off;
        int c = g_counts[e];
        for (int r = 0; r < c; r += TILE) {
            g_tile_expert[nt] = e;
            g_tile_row0[nt]  = off + r;
            g_tile_rows[nt]  = min(TILE, c - r);
            nt++;
        }
        off += c;
        g_cursor[e] = 0;
    }
    g_offs[E_] = off;
    for (; nt < MAX_MT; nt++) g_tile_rows[nt] = 0;
}

// ---------------- kernel 3: scatter tokens by expert ----------------
__global__ void scatter_kernel() {
    int t = blockIdx.x * blockDim.x + threadIdx.x;
    if (t >= T_) return;
    int e = g_expert_idx[t];
    int pos = g_offs[e] + atomicAdd(&g_cursor[e], 1);
    g_perm[pos] = t;
}

// ---------------- GELU (tanh approx, matching jax.nn.gelu default) ----------------
__device__ __forceinline__ float gelu_tanh(float v) {
    float v3 = v * v * v;
    float t = tanhf(0.7978845608028654f * (v + 0.044715f * v3));
    return 0.5f * v * (1.0f + t);
}

// ---------------- grouped FFN GEMM: [rows<=128] x [K,N] tile ----------------
// Y[tok, n0+cj] = act( sum_k X[tok,k] * W[e][k, n] + bias[e][n] )
template <int K, int N, bool GELU>
__global__ void __launch_bounds__(256)
ffn_kernel(const float* __restrict__ X, int ldx,
           const float* __restrict__ Wb,   // per-expert stride K*N
           const float* __restrict__ Bb,   // per-expert stride N
           float* __restrict__ Y, int ldy) {
    int mt = blockIdx.y;
    int rows = g_tile_rows[mt];
    if (rows == 0) return;
    int e    = g_tile_expert[mt];
    int row0 = g_tile_row0[mt];
    const float* W    = Wb + (size_t)e * K * N;
    const float* bias = Bb + (size_t)e * N;
    int n0 = blockIdx.x * TILE;

    __shared__ float As[KC][TILE + 4];
    __shared__ float Bs[KC][TILE + 4];
    __shared__ int   s_tok[TILE];

    int tid = threadIdx.x;
    if (tid < TILE) {
        int m = tid;
        s_tok[m] = g_perm[row0 + ((m < rows) ? m : 0)];  // dup a valid row for padding
    }
    __syncthreads();

    int tx = tid & 15;       // col group
    int ty = tid >> 4;       // row group
    // A loader: lm = row, lk = k quad
    int lm = tid >> 1;             // 0..127
    int lk = (tid & 1) * 4;        // 0 or 4
    // B loader
    int lkb = tid >> 5;            // 0..7
    int lnq = (tid & 31) * 4;      // 0..124

    const float* arow = X + (size_t)s_tok[lm] * ldx + lk;

    float acc[8][8];
#pragma unroll
    for (int i = 0; i < 8; i++)
#pragma unroll
        for (int j = 0; j < 8; j++) acc[i][j] = 0.f;

    for (int k0 = 0; k0 < K; k0 += KC) {
        float4 av = *(const float4*)(arow + k0);
        As[lk + 0][lm] = av.x;
        As[lk + 1][lm] = av.y;
        As[lk + 2][lm] = av.z;
        As[lk + 3][lm] = av.w;
        float4 bv = *(const float4*)(W + (size_t)(k0 + lkb) * N + n0 + lnq);
        *(float4*)&Bs[lkb][lnq] = bv;
        __syncthreads();
#pragma unroll
        for (int kk = 0; kk < KC; kk++) {
            float4 a0 = *(const float4*)&As[kk][4 * ty];
            float4 a1 = *(const float4*)&As[kk][4 * ty + 64];
            float4 b0 = *(const float4*)&Bs[kk][4 * tx];
            float4 b1 = *(const float4*)&Bs[kk][4 * tx + 64];
            float a[8] = {a0.x, a0.y, a0.z, a0.w, a1.x, a1.y, a1.z, a1.w};
            float b[8] = {b0.x, b0.y, b0.z, b0.w, b1.x, b1.y, b1.z, b1.w};
#pragma unroll
            for (int i = 0; i < 8; i++)
#pragma unroll
                for (int j = 0; j < 8; j++)
                    acc[i][j] = fmaf(a[i], b[j], acc[i][j]);
        }
        __syncthreads();
    }

    // epilogue
#pragma unroll
    for (int i = 0; i < 8; i++) {
        int m = (i < 4) ? (4 * ty + i) : (64 + 4 * ty + (i - 4));
        if (m < rows) {
            int tok = s_tok[m];
            float* yrow = Y + (size_t)tok * ldy;
#pragma unroll
            for (int j = 0; j < 8; j++) {
                int cj = (j < 4) ? (4 * tx + j) : (64 + 4 * tx + (j - 4));
                int n = n0 + cj;
                float v = acc[i][j] + bias[n];
                if (GELU) v = gelu_tanh(v);
                yrow[n] = v;
            }
        }
    }
}

// ---------------- launch ----------------
extern "C" void kernel_launch(void* const* d_in, const int* in_sizes, int n_in,
                              void* d_out, int out_size) {
    const float* x      = (const float*)d_in[0];
    const float* gumbel = (const float*)d_in[1];
    const float* Wg     = (const float*)d_in[2];
    const float* bg     = (const float*)d_in[3];
    const float* W1     = (const float*)d_in[4];
    const float* b1     = (const float*)d_in[5];
    const float* W2     = (const float*)d_in[6];
    const float* b2     = (const float*)d_in[7];
    float* out = (float*)d_out;

    float* hbuf;
    cudaGetSymbolAddress((void**)&hbuf, g_h);

    init_kernel<<<1, 32>>>();
    gate_kernel<<<T_ / 8, 256>>>(x, gumbel, Wg, bg);        // 8 warps/block
    scan_kernel<<<1, 32>>>();
    scatter_kernel<<<T_ / 256, 256>>>();
    // FFN1: [T,768] x [768,3072] + GELU -> g_h
    ffn_kernel<D_, H_, true><<<dim3(H_ / TILE, MAX_MT), 256>>>(x, D_, W1, b1, hbuf, H_);
    // FFN2: [T,3072] x [3072,768] -> out
    ffn_kernel<H_, D_, false><<<dim3(D_ / TILE, MAX_MT), 256>>>(hbuf, H_, W2, b2, out, D_);
}

// round 5
// speedup vs baseline: 2.4906x; 2.4906x over previous
#include <cuda_runtime.h>
#include <cuda_bf16.h>
#include <math.h>
#include <stdint.h>

// Problem dims
#define B_ 4
#define S_ 2048
#define T_ 8192      // B*S tokens
#define D_ 768
#define H_ 3072
#define E_ 8

#define TILE 128
#define MAX_MT 72    // worst-case sum over experts of ceil(n_e/128)

// ---------------- scratch (no allocations allowed) ----------------
__device__ int   g_expert_idx[T_];
__device__ int   g_counts[E_];
__device__ int   g_offs[E_ + 1];
__device__ int   g_cursor[E_];
__device__ int   g_perm[T_];
__device__ int   g_tile_expert[MAX_MT];
__device__ int   g_tile_row0[MAX_MT];
__device__ int   g_tile_rows[MAX_MT];
__device__ __align__(16) float g_h[(size_t)T_ * H_];          // hidden, sorted order (tf32-rounded)
__device__ __align__(16) float g_gx[(size_t)T_ * D_];         // gathered x, sorted (tf32-rounded)
__device__ __align__(16) float g_w1t[(size_t)E_ * H_ * D_];   // W1^T [e][n=H][k=D] (tf32-rounded)
__device__ __align__(16) float g_w2t[(size_t)E_ * D_ * H_];   // W2^T [e][n=D][k=H] (tf32-rounded)

// ---------------- helpers ----------------
__device__ __forceinline__ uint32_t smem_u32(const void* p) {
    uint32_t a;
    asm("{ .reg .u64 t; cvta.to.shared.u64 t, %1; cvt.u32.u64 %0, t; }" : "=r"(a) : "l"(p));
    return a;
}
__device__ __forceinline__ float tf32r(float f) {   // round-to-nearest tf32 (unbiased)
    uint32_t u;
    asm("cvt.rna.tf32.f32 %0, %1;" : "=r"(u) : "f"(f));
    return __uint_as_float(u);
}
__device__ __forceinline__ void cp16(uint32_t s, const void* g) {
    asm volatile("cp.async.cg.shared.global [%0], [%1], 16;" :: "r"(s), "l"(g));
}
__device__ __forceinline__ void cp_commit() {
    asm volatile("cp.async.commit_group;" ::: "memory");
}
template <int N> __device__ __forceinline__ void cp_wait() {
    asm volatile("cp.async.wait_group %0;" :: "n"(N) : "memory");
}
// m16n8k8 tf32 mma.sync (row.col): D += A*B
__device__ __forceinline__ void mma8(float* c, const uint32_t* a, const uint32_t* b) {
    asm volatile(
        "mma.sync.aligned.m16n8k8.row.col.f32.tf32.tf32.f32 "
        "{%0,%1,%2,%3}, {%4,%5,%6,%7}, {%8,%9}, {%0,%1,%2,%3};"
        : "+f"(c[0]), "+f"(c[1]), "+f"(c[2]), "+f"(c[3])
        : "r"(a[0]), "r"(a[1]), "r"(a[2]), "r"(a[3]), "r"(b[0]), "r"(b[1]));
}

// ---------------- kernel 0: init ----------------
__global__ void init_kernel() {
    int i = threadIdx.x;
    if (i < E_) g_counts[i] = 0;
}

// ---------------- kernel 1: gating (argmax(x@Wg + bg + gumbel)) ----------------
__global__ void gate_kernel(const float* __restrict__ x,
                            const float* __restrict__ gumbel,
                            const float* __restrict__ Wg,
                            const float* __restrict__ bg) {
    int warp = (blockIdx.x * blockDim.x + threadIdx.x) >> 5;
    int lane = threadIdx.x & 31;
    if (warp >= T_) return;
    const float* xr = x + (size_t)warp * D_;
    float acc[E_];
#pragma unroll
    for (int e = 0; e < E_; e++) acc[e] = 0.f;
    for (int d = lane; d < D_; d += 32) {
        float xv = xr[d];
        float4 w0 = *(const float4*)(Wg + d * E_);
        float4 w1 = *(const float4*)(Wg + d * E_ + 4);
        acc[0] = fmaf(xv, w0.x, acc[0]);
        acc[1] = fmaf(xv, w0.y, acc[1]);
        acc[2] = fmaf(xv, w0.z, acc[2]);
        acc[3] = fmaf(xv, w0.w, acc[3]);
        acc[4] = fmaf(xv, w1.x, acc[4]);
        acc[5] = fmaf(xv, w1.y, acc[5]);
        acc[6] = fmaf(xv, w1.z, acc[6]);
        acc[7] = fmaf(xv, w1.w, acc[7]);
    }
#pragma unroll
    for (int e = 0; e < E_; e++) {
#pragma unroll
        for (int off = 16; off; off >>= 1)
            acc[e] += __shfl_xor_sync(0xFFFFFFFFu, acc[e], off);
    }
    if (lane == 0) {
        const float* g = gumbel + (size_t)warp * E_;
        int best = 0;
        float bv = acc[0] + bg[0] + g[0];
#pragma unroll
        for (int e = 1; e < E_; e++) {
            float v = acc[e] + bg[e] + g[e];
            if (v > bv) { bv = v; best = e; }   // strict > keeps first max (jnp.argmax)
        }
        g_expert_idx[warp] = best;
        atomicAdd(&g_counts[best], 1);
    }
}

// ---------------- kernel 2: scan + tile table ----------------
__global__ void scan_kernel() {
    if (threadIdx.x != 0) return;
    int off = 0, nt = 0;
    for (int e = 0; e < E_; e++) {
        g_offs[e] = off;
        int c = g_counts[e];
        for (int r = 0; r < c; r += TILE) {
            g_tile_expert[nt] = e;
            g_tile_row0[nt]  = off + r;
            g_tile_rows[nt]  = min(TILE, c - r);
            nt++;
        }
        off += c;
        g_cursor[e] = 0;
    }
    g_offs[E_] = off;
    for (; nt < MAX_MT; nt++) g_tile_rows[nt] = 0;
}

// ---------------- kernel 3: scatter tokens by expert ----------------
__global__ void scatter_kernel() {
    int t = blockIdx.x * blockDim.x + threadIdx.x;
    if (t >= T_) return;
    int e = g_expert_idx[t];
    int pos = g_offs[e] + atomicAdd(&g_cursor[e], 1);
    g_perm[pos] = t;
}

// ---------------- kernel 4: gather x rows into sorted order + tf32 round ----------------
__global__ void gather_rna_kernel(const float* __restrict__ x) {
    int row = blockIdx.x;            // 0..T_-1 (sorted position)
    int t   = threadIdx.x;           // 0..191, 4 floats each
    int src = g_perm[row];
    float4 v = *(const float4*)(x + (size_t)src * D_ + 4 * t);
    v.x = tf32r(v.x); v.y = tf32r(v.y); v.z = tf32r(v.z); v.w = tf32r(v.w);
    *(float4*)(g_gx + (size_t)row * D_ + 4 * t) = v;
}

// ---------------- kernel 5: weight transpose [e][K][N] -> [e][N][K] + tf32 round ----------------
__global__ void transpose_rna_kernel(const float* __restrict__ W, float* __restrict__ Wt,
                                     int K, int N) {
    __shared__ float tile[32][33];
    int e = blockIdx.z;
    int n0 = blockIdx.x * 32, k0 = blockIdx.y * 32;
    const float* Ws = W  + (size_t)e * K * N;
    float*       Wd = Wt + (size_t)e * N * K;
    int x = threadIdx.x, y = threadIdx.y;
#pragma unroll
    for (int i = y; i < 32; i += 8)
        tile[i][x] = Ws[(size_t)(k0 + i) * N + n0 + x];
    __syncthreads();
#pragma unroll
    for (int i = y; i < 32; i += 8)
        Wd[(size_t)(n0 + i) * K + k0 + x] = tf32r(tile[x][i]);
}

// ---------------- GELU (tanh approx, matches jax.nn.gelu default) ----------------
__device__ __forceinline__ float gelu_tanh(float v) {
    float v3 = v * v * v;
    float t = tanhf(0.7978845608028654f * (v + 0.044715f * v3));
    return 0.5f * v * (1.0f + t);
}

// ================= mma.sync tf32 grouped GEMM =================
// Y[128-tile, NTOT] for one (m-tile, n-block): A sorted-contiguous [.][K],
// B K-major [E][NTOT][K] (pre-transposed, tf32-rounded). BM=128, BN=128, BK=16.
// 8 warps as 2(m) x 4(n); warp tile 64x32 = 4x4 m16n8k8 fragments.
#define BK 16
#define LDK 20          // padded k-stride in floats (bank-conflict-free fragments)
#define TILE_FLOATS (128 * LDK)        // 2560 floats per operand tile
#define BUF_FLOATS  (2 * TILE_FLOATS)  // A + B per buffer

template <int K, int NTOT, bool GELU_, bool SCATTER>
__global__ void __launch_bounds__(256, 2)
mma_gemm_kernel(const float* __restrict__ A,
                const float* __restrict__ Bw,
                const float* __restrict__ bias_all,
                float* __restrict__ Y) {
    constexpr int KT = K / BK;

    int mt = blockIdx.y;
    int rows = g_tile_rows[mt];
    if (rows == 0) return;
    int e    = g_tile_expert[mt];
    int row0 = g_tile_row0[mt];
    int n0   = blockIdx.x * 128;

    extern __shared__ float smf[];
    uint32_t su = smem_u32(smf);
    __shared__ int s_tok[TILE];

    int tid  = threadIdx.x;
    int wid  = tid >> 5;
    int lane = tid & 31;
    int tq   = lane >> 2;      // groupID   0..7
    int tr   = lane & 3;       // tid-in-group 0..3
    int wm0  = (wid & 1) * 64; // warp m origin
    int wn0  = (wid >> 1) * 32;// warp n origin

    if (SCATTER && tid < TILE)
        s_tok[tid] = (tid < rows) ? g_perm[row0 + tid] : 0;

    const float* Arow = A  + (size_t)row0 * K;              // m-tile base
    const float* Brow = Bw + ((size_t)e * NTOT + n0) * K;   // n-block base

    // --- tile loader: buffer s, k-chunk kt ---
    auto load_tiles = [&](int kt, int s) {
        const int k0 = kt * BK;
        uint32_t abase = su + (uint32_t)(s * BUF_FLOATS) * 4u;
        uint32_t bbase = abase + (uint32_t)TILE_FLOATS * 4u;
#pragma unroll
        for (int it = 0; it < 2; it++) {
            int idx = tid + it * 256;          // 0..511
            int row = idx >> 2, c4 = idx & 3;  // 128 rows x 4 float4
            int rg = row; if (row0 + rg > T_ - 1) rg = (T_ - 1) - row0;  // clamp (dup row)
            cp16(abase + (uint32_t)(row * LDK + c4 * 4) * 4u,
                 Arow + (size_t)rg * K + k0 + c4 * 4);
            cp16(bbase + (uint32_t)(row * LDK + c4 * 4) * 4u,
                 Brow + (size_t)row * K + k0 + c4 * 4);
        }
    };

    float c[4][4][4];
#pragma unroll
    for (int i = 0; i < 4; i++)
#pragma unroll
        for (int j = 0; j < 4; j++)
#pragma unroll
            for (int r = 0; r < 4; r++) c[i][j][r] = 0.f;

    load_tiles(0, 0);
    cp_commit();

    for (int kt = 0; kt < KT; kt++) {
        int s = kt & 1;
        if (kt + 1 < KT) {
            load_tiles(kt + 1, (kt + 1) & 1);
            cp_commit();
            cp_wait<1>();      // chunk kt resident
        } else {
            cp_wait<0>();
        }
        __syncthreads();

        const float* Abuf = smf + s * BUF_FLOATS;
        const float* Bbuf = Abuf + TILE_FLOATS;
#pragma unroll
        for (int ks = 0; ks < 2; ks++) {
            const int k0 = ks * 8;
            uint32_t a[4][4], b[4][2];
            const float* ap = Abuf + (wm0 + tq) * LDK + k0 + tr;
#pragma unroll
            for (int i = 0; i < 4; i++) {
                a[i][0] = __float_as_uint(ap[(16 * i    ) * LDK]);
                a[i][1] = __float_as_uint(ap[(16 * i + 8) * LDK]);
                a[i][2] = __float_as_uint(ap[(16 * i    ) * LDK + 4]);
                a[i][3] = __float_as_uint(ap[(16 * i + 8) * LDK + 4]);
            }
            const float* bp = Bbuf + (wn0 + tq) * LDK + k0 + tr;
#pragma unroll
            for (int j = 0; j < 4; j++) {
                b[j][0] = __float_as_uint(bp[(8 * j) * LDK]);
                b[j][1] = __float_as_uint(bp[(8 * j) * LDK + 4]);
            }
#pragma unroll
            for (int i = 0; i < 4; i++)
#pragma unroll
                for (int j = 0; j < 4; j++)
                    mma8(c[i][j], a[i], b[j]);
        }
        __syncthreads();
    }

    // --- epilogue ---
    const float* brow = bias_all + (size_t)e * NTOT + n0;
#pragma unroll
    for (int i = 0; i < 4; i++) {
#pragma unroll
        for (int half = 0; half < 2; half++) {       // c0/c1 (row) vs c2/c3 (row+8)
            int m = wm0 + 16 * i + tq + 8 * half;
            if (m >= rows) continue;
            int dst_row = SCATTER ? s_tok[m] : (row0 + m);
            float* yrow = Y + (size_t)dst_row * NTOT + n0;
#pragma unroll
            for (int j = 0; j < 4; j++) {
                int col = wn0 + 8 * j + 2 * tr;
                float v0 = c[i][j][2 * half + 0] + brow[col];
                float v1 = c[i][j][2 * half + 1] + brow[col + 1];
                if (GELU_) {                  // h is FFN2's A operand -> round to tf32
                    v0 = tf32r(gelu_tanh(v0));
                    v1 = tf32r(gelu_tanh(v1));
                }
                float2 st = {v0, v1};
                *(float2*)(yrow + col) = st;
            }
        }
    }
}

// ---------------- launch ----------------
extern "C" void kernel_launch(void* const* d_in, const int* in_sizes, int n_in,
                              void* d_out, int out_size) {
    const float* x      = (const float*)d_in[0];
    const float* gumbel = (const float*)d_in[1];
    const float* Wg     = (const float*)d_in[2];
    const float* bg     = (const float*)d_in[3];
    const float* W1     = (const float*)d_in[4];
    const float* b1     = (const float*)d_in[5];
    const float* W2     = (const float*)d_in[6];
    const float* b2     = (const float*)d_in[7];
    float* out = (float*)d_out;

    float *hbuf, *gxbuf, *w1t, *w2t;
    cudaGetSymbolAddress((void**)&hbuf,  g_h);
    cudaGetSymbolAddress((void**)&gxbuf, g_gx);
    cudaGetSymbolAddress((void**)&w1t,   g_w1t);
    cudaGetSymbolAddress((void**)&w2t,   g_w2t);

    // routing
    init_kernel<<<1, 32>>>();
    gate_kernel<<<T_ / 8, 256>>>(x, gumbel, Wg, bg);
    scan_kernel<<<1, 32>>>();
    scatter_kernel<<<T_ / 256, 256>>>();

    // operand staging (tf32 rna-rounded)
    gather_rna_kernel<<<T_, 192>>>(x);
    transpose_rna_kernel<<<dim3(H_ / 32, D_ / 32, E_), dim3(32, 8)>>>(W1, w1t, D_, H_);
    transpose_rna_kernel<<<dim3(D_ / 32, H_ / 32, E_), dim3(32, 8)>>>(W2, w2t, H_, D_);

    constexpr int SMEM = 2 * BUF_FLOATS * 4;   // 40960 B (< 48K, no attribute needed)

    // FFN1: h = gelu(gx @ W1^T + b1), sorted order
    mma_gemm_kernel<D_, H_, true, false>
        <<<dim3(H_ / 128, MAX_MT), 256, SMEM>>>(gxbuf, w1t, b1, hbuf);

    // FFN2: out = h @ W2^T + b2, scattered to token order
    mma_gemm_kernel<H_, D_, false, true>
        <<<dim3(D_ / 128, MAX_MT), 256, SMEM>>>(hbuf, w2t, b2, out);
}

// round 10
// speedup vs baseline: 4.2465x; 1.7050x over previous
#include <cuda_runtime.h>
#include <cuda_fp16.h>
#include <math.h>
#include <stdint.h>

// Problem dims
#define B_ 4
#define S_ 2048
#define T_ 8192      // B*S tokens
#define D_ 768
#define H_ 3072
#define E_ 8

#define TILE 128
#define MAX_MT 72    // worst-case sum over experts of ceil(n_e/128)

// ---------------- scratch (no allocations allowed) ----------------
__device__ int   g_expert_idx[T_];
__device__ int   g_counts[E_];
__device__ int   g_offs[E_ + 1];
__device__ int   g_cursor[E_];
__device__ int   g_perm[T_];
__device__ int   g_tile_expert[MAX_MT];
__device__ int   g_tile_row0[MAX_MT];
__device__ int   g_tile_rows[MAX_MT];
__device__ __align__(16) __half g_hh[(size_t)T_ * H_];         // hidden, sorted order (fp16)
__device__ __align__(16) __half g_gx[(size_t)T_ * D_];         // gathered x, sorted (fp16)
__device__ __align__(16) __half g_w1t[(size_t)E_ * H_ * D_];   // W1^T [e][n=H][k=D] (fp16)
__device__ __align__(16) __half g_w2t[(size_t)E_ * D_ * H_];   // W2^T [e][n=D][k=H] (fp16)

// ---------------- helpers ----------------
__device__ __forceinline__ uint32_t smem_u32(const void* p) {
    uint32_t a;
    asm("{ .reg .u64 t; cvta.to.shared.u64 t, %1; cvt.u32.u64 %0, t; }" : "=r"(a) : "l"(p));
    return a;
}
__device__ __forceinline__ void cp16(uint32_t s, const void* g) {
    asm volatile("cp.async.cg.shared.global [%0], [%1], 16;" :: "r"(s), "l"(g));
}
__device__ __forceinline__ void cp_commit() {
    asm volatile("cp.async.commit_group;" ::: "memory");
}
template <int N> __device__ __forceinline__ void cp_wait() {
    asm volatile("cp.async.wait_group %0;" :: "n"(N) : "memory");
}
// m16n8k16 fp16 mma.sync (row.col), fp32 accumulate
__device__ __forceinline__ void mma16(float* c, const uint32_t* a, const uint32_t* b) {
    asm volatile(
        "mma.sync.aligned.m16n8k16.row.col.f32.f16.f16.f32 "
        "{%0,%1,%2,%3}, {%4,%5,%6,%7}, {%8,%9}, {%0,%1,%2,%3};"
        : "+f"(c[0]), "+f"(c[1]), "+f"(c[2]), "+f"(c[3])
        : "r"(a[0]), "r"(a[1]), "r"(a[2]), "r"(a[3]), "r"(b[0]), "r"(b[1]));
}

// ---------------- kernel 0: init ----------------
__global__ void init_kernel() {
    int i = threadIdx.x;
    if (i < E_) g_counts[i] = 0;
}

// ---------------- kernel 1: gating (argmax(x@Wg + bg + gumbel)) ----------------
__global__ void gate_kernel(const float* __restrict__ x,
                            const float* __restrict__ gumbel,
                            const float* __restrict__ Wg,
                            const float* __restrict__ bg) {
    int warp = (blockIdx.x * blockDim.x + threadIdx.x) >> 5;
    int lane = threadIdx.x & 31;
    if (warp >= T_) return;
    const float* xr = x + (size_t)warp * D_;
    float acc[E_];
#pragma unroll
    for (int e = 0; e < E_; e++) acc[e] = 0.f;
    for (int d = lane; d < D_; d += 32) {
        float xv = xr[d];
        float4 w0 = *(const float4*)(Wg + d * E_);
        float4 w1 = *(const float4*)(Wg + d * E_ + 4);
        acc[0] = fmaf(xv, w0.x, acc[0]);
        acc[1] = fmaf(xv, w0.y, acc[1]);
        acc[2] = fmaf(xv, w0.z, acc[2]);
        acc[3] = fmaf(xv, w0.w, acc[3]);
        acc[4] = fmaf(xv, w1.x, acc[4]);
        acc[5] = fmaf(xv, w1.y, acc[5]);
        acc[6] = fmaf(xv, w1.z, acc[6]);
        acc[7] = fmaf(xv, w1.w, acc[7]);
    }
#pragma unroll
    for (int e = 0; e < E_; e++) {
#pragma unroll
        for (int off = 16; off; off >>= 1)
            acc[e] += __shfl_xor_sync(0xFFFFFFFFu, acc[e], off);
    }
    if (lane == 0) {
        const float* g = gumbel + (size_t)warp * E_;
        int best = 0;
        float bv = acc[0] + bg[0] + g[0];
#pragma unroll
        for (int e = 1; e < E_; e++) {
            float v = acc[e] + bg[e] + g[e];
            if (v > bv) { bv = v; best = e; }   // strict > keeps first max (jnp.argmax)
        }
        g_expert_idx[warp] = best;
        atomicAdd(&g_counts[best], 1);
    }
}

// ---------------- kernel 2: scan + tile table ----------------
__global__ void scan_kernel() {
    if (threadIdx.x != 0) return;
    int off = 0, nt = 0;
    for (int e = 0; e < E_; e++) {
        g_offs[e] = off;
        int c = g_counts[e];
        for (int r = 0; r < c; r += TILE) {
            g_tile_expert[nt] = e;
            g_tile_row0[nt]  = off + r;
            g_tile_rows[nt]  = min(TILE, c - r);
            nt++;
        }
        off += c;
        g_cursor[e] = 0;
    }
    g_offs[E_] = off;
    for (; nt < MAX_MT; nt++) g_tile_rows[nt] = 0;
}

// ---------------- kernel 3: scatter tokens by expert ----------------
__global__ void scatter_kernel() {
    int t = blockIdx.x * blockDim.x + threadIdx.x;
    if (t >= T_) return;
    int e = g_expert_idx[t];
    int pos = g_offs[e] + atomicAdd(&g_cursor[e], 1);
    g_perm[pos] = t;
}

// ---------------- kernel 4: gather x rows into sorted order + fp16 ----------------
__global__ void gather_h_kernel(const float* __restrict__ x) {
    int row = blockIdx.x;            // 0..T_-1 (sorted position)
    int t   = threadIdx.x;           // 0..191, 4 floats each
    int src = g_perm[row];
    float4 v = *(const float4*)(x + (size_t)src * D_ + 4 * t);
    __half2 h0 = __floats2half2_rn(v.x, v.y);
    __half2 h1 = __floats2half2_rn(v.z, v.w);
    *(uint2*)(g_gx + (size_t)row * D_ + 4 * t) = make_uint2(
        *(const uint32_t*)&h0, *(const uint32_t*)&h1);
}

// ---------------- kernel 5: weight transpose [e][K][N] -> [e][N][K] + fp16 ----------------
__global__ void transpose_h_kernel(const float* __restrict__ W, __half* __restrict__ Wt,
                                   int K, int N) {
    __shared__ float tile[32][33];
    int e = blockIdx.z;
    int n0 = blockIdx.x * 32, k0 = blockIdx.y * 32;
    const float* Ws = W  + (size_t)e * K * N;
    __half*      Wd = Wt + (size_t)e * N * K;
    int x = threadIdx.x, y = threadIdx.y;
#pragma unroll
    for (int i = y; i < 32; i += 8)
        tile[i][x] = Ws[(size_t)(k0 + i) * N + n0 + x];
    __syncthreads();
#pragma unroll
    for (int i = y; i < 32; i += 8)
        Wd[(size_t)(n0 + i) * K + k0 + x] = __float2half_rn(tile[x][i]);
}

// ---------------- GELU (tanh approx, matches jax.nn.gelu default) ----------------
__device__ __forceinline__ float gelu_tanh(float v) {
    float v3 = v * v * v;
    float t = tanhf(0.7978845608028654f * (v + 0.044715f * v3));
    return 0.5f * v * (1.0f + t);
}

// ================= fp16 mma.sync grouped GEMM =================
// Y[128-tile, NTOT]: A sorted-contiguous fp16 [.][K], B K-major fp16 [E][NTOT][K].
// BM=128, BN=128, BK=32 halves. 8 warps as 2(m) x 4(n); warp tile 64x32
// = 4x4 m16n8k16 fragments per k16-step, 2 steps per chunk.
#define BKH 32          // halves per k-chunk
#define LDKH 40         // padded row stride in halves (80 B: conflict-free mod 128)
#define TILE_HALVES (128 * LDKH)        // 5120 halves per operand tile
#define BUF_HALVES  (2 * TILE_HALVES)   // A + B per buffer

template <int K, int NTOT, bool GELU_, bool SCATTER, typename OutT>
__global__ void __launch_bounds__(256, 2)
mma_gemm_kernel(const __half* __restrict__ A,
                const __half* __restrict__ Bw,
                const float* __restrict__ bias_all,
                OutT* __restrict__ Y) {
    constexpr int KT = K / BKH;

    int mt = blockIdx.y;
    int rows = g_tile_rows[mt];
    if (rows == 0) return;
    int e    = g_tile_expert[mt];
    int row0 = g_tile_row0[mt];
    int n0   = blockIdx.x * 128;

    extern __shared__ __half smh[];
    uint32_t su = smem_u32(smh);
    __shared__ int s_tok[TILE];

    int tid  = threadIdx.x;
    int wid  = tid >> 5;
    int lane = tid & 31;
    int tq   = lane >> 2;      // groupID   0..7
    int tr   = lane & 3;       // tid-in-group 0..3
    int wm0  = (wid & 1) * 64; // warp m origin
    int wn0  = (wid >> 1) * 32;// warp n origin

    if (SCATTER && tid < TILE)
        s_tok[tid] = (tid < rows) ? g_perm[row0 + tid] : 0;

    const __half* Arow = A  + (size_t)row0 * K;              // m-tile base
    const __half* Brow = Bw + ((size_t)e * NTOT + n0) * K;   // n-block base

    // --- tile loader: buffer s, k-chunk kt (BKH halves = 64 B/row = 4 cp16) ---
    auto load_tiles = [&](int kt, int s) {
        const int k0 = kt * BKH;
        uint32_t abase = su + (uint32_t)(s * BUF_HALVES) * 2u;
        uint32_t bbase = abase + (uint32_t)TILE_HALVES * 2u;
#pragma unroll
        for (int it = 0; it < 2; it++) {
            int idx = tid + it * 256;          // 0..511
            int row = idx >> 2, c4 = idx & 3;  // 128 rows x 4 x 16B
            int rg = row; if (row0 + rg > T_ - 1) rg = (T_ - 1) - row0;  // clamp (dup row)
            cp16(abase + (uint32_t)(row * LDKH) * 2u + c4 * 16u,
                 Arow + (size_t)rg * K + k0 + c4 * 8);
            cp16(bbase + (uint32_t)(row * LDKH) * 2u + c4 * 16u,
                 Brow + (size_t)row * K + k0 + c4 * 8);
        }
    };

    float c[4][4][4];
#pragma unroll
    for (int i = 0; i < 4; i++)
#pragma unroll
        for (int j = 0; j < 4; j++)
#pragma unroll
            for (int r = 0; r < 4; r++) c[i][j][r] = 0.f;

    load_tiles(0, 0);
    cp_commit();

    for (int kt = 0; kt < KT; kt++) {
        int s = kt & 1;
        if (kt + 1 < KT) {
            load_tiles(kt + 1, (kt + 1) & 1);
            cp_commit();
            cp_wait<1>();      // chunk kt resident
        } else {
            cp_wait<0>();
        }
        __syncthreads();

        const __half* Abuf = smh + s * BUF_HALVES;
        const __half* Bbuf = Abuf + TILE_HALVES;
#pragma unroll
        for (int ks = 0; ks < 2; ks++) {
            const int k0 = ks * 16;
            uint32_t a[4][4], b[4][2];
            const __half* ap = Abuf + (wm0 + tq) * LDKH + k0 + 2 * tr;
#pragma unroll
            for (int i = 0; i < 4; i++) {
                a[i][0] = *(const uint32_t*)(ap + (16 * i    ) * LDKH);
                a[i][1] = *(const uint32_t*)(ap + (16 * i + 8) * LDKH);
                a[i][2] = *(const uint32_t*)(ap + (16 * i    ) * LDKH + 8);
                a[i][3] = *(const uint32_t*)(ap + (16 * i + 8) * LDKH + 8);
            }
            const __half* bp = Bbuf + (wn0 + tq) * LDKH + k0 + 2 * tr;
#pragma unroll
            for (int j = 0; j < 4; j++) {
                b[j][0] = *(const uint32_t*)(bp + (8 * j) * LDKH);
                b[j][1] = *(const uint32_t*)(bp + (8 * j) * LDKH + 8);
            }
#pragma unroll
            for (int i = 0; i < 4; i++)
#pragma unroll
                for (int j = 0; j < 4; j++)
                    mma16(c[i][j], a[i], b[j]);
        }
        __syncthreads();
    }

    // --- epilogue ---
    const float* brow = bias_all + (size_t)e * NTOT + n0;
#pragma unroll
    for (int i = 0; i < 4; i++) {
#pragma unroll
        for (int half = 0; half < 2; half++) {       // c0/c1 (row tq) vs c2/c3 (row tq+8)
            int m = wm0 + 16 * i + tq + 8 * half;
            if (m >= rows) continue;
            int dst_row = SCATTER ? s_tok[m] : (row0 + m);
            OutT* yrow = Y + (size_t)dst_row * NTOT + n0;
#pragma unroll
            for (int j = 0; j < 4; j++) {
                int col = wn0 + 8 * j + 2 * tr;
                float v0 = c[i][j][2 * half + 0] + brow[col];
                float v1 = c[i][j][2 * half + 1] + brow[col + 1];
                if (GELU_) {
                    v0 = gelu_tanh(v0);
                    v1 = gelu_tanh(v1);
                }
                if (sizeof(OutT) == 2) {             // fp16 h (A operand of FFN2)
                    __half2 hv = __floats2half2_rn(v0, v1);
                    *(__half2*)((__half*)yrow + col) = hv;
                } else {
                    float2 st = {v0, v1};
                    *(float2*)((float*)yrow + col) = st;
                }
            }
        }
    }
}

// ---------------- launch ----------------
extern "C" void kernel_launch(void* const* d_in, const int* in_sizes, int n_in,
                              void* d_out, int out_size) {
    const float* x      = (const float*)d_in[0];
    const float* gumbel = (const float*)d_in[1];
    const float* Wg     = (const float*)d_in[2];
    const float* bg     = (const float*)d_in[3];
    const float* W1     = (const float*)d_in[4];
    const float* b1     = (const float*)d_in[5];
    const float* W2     = (const float*)d_in[6];
    const float* b2     = (const float*)d_in[7];
    float* out = (float*)d_out;

    __half *hbuf, *gxbuf, *w1t, *w2t;
    cudaGetSymbolAddress((void**)&hbuf,  g_hh);
    cudaGetSymbolAddress((void**)&gxbuf, g_gx);
    cudaGetSymbolAddress((void**)&w1t,   g_w1t);
    cudaGetSymbolAddress((void**)&w2t,   g_w2t);

    // routing
    init_kernel<<<1, 32>>>();
    gate_kernel<<<T_ / 8, 256>>>(x, gumbel, Wg, bg);
    scan_kernel<<<1, 32>>>();
    scatter_kernel<<<T_ / 256, 256>>>();

    // operand staging (fp16 rn)
    gather_h_kernel<<<T_, 192>>>(x);
    transpose_h_kernel<<<dim3(H_ / 32, D_ / 32, E_), dim3(32, 8)>>>(W1, w1t, D_, H_);
    transpose_h_kernel<<<dim3(D_ / 32, H_ / 32, E_), dim3(32, 8)>>>(W2, w2t, H_, D_);

    constexpr int SMEM = 2 * BUF_HALVES * 2;   // 40960 B

    // FFN1: h = gelu(gx @ W1^T + b1), sorted order, fp16 out
    mma_gemm_kernel<D_, H_, true, false, __half>
        <<<dim3(H_ / 128, MAX_MT), 256, SMEM>>>(gxbuf, w1t, b1, hbuf);

    // FFN2: out = h @ W2^T + b2, scattered to token order, fp32 out
    mma_gemm_kernel<H_, D_, false, true, float>
        <<<dim3(D_ / 128, MAX_MT), 256, SMEM>>>(hbuf, w2t, b2, out);
}